// round 5
// baseline (speedup 1.0000x reference)
#include <cuda_runtime.h>
#include <math.h>

#define SEQ 50
#define DIM 32
#define NTHR 128
#define PITCH 36          // row pitch in floats: 144B = 4-bank shift per row
#define FULLM 0xffffffffu

// Folded weights, shared by all batches (computed once by prep_kernel)
__device__ float gWfold[3 * DIM * DIM];   // rows pre-scaled by ln_g
__device__ float gB2[3 * DIM];            // bias + b . W^T
__device__ float gSw[3 * DIM];            // rowsum of g-scaled W

__global__ void prep_kernel(
    const float* __restrict__ ln_g, const float* __restrict__ ln_b,
    const float* __restrict__ Wq, const float* __restrict__ bq,
    const float* __restrict__ Wk, const float* __restrict__ bk,
    const float* __restrict__ Wv, const float* __restrict__ bv)
{
    int j = threadIdx.x;
    if (j >= 3 * DIM) return;
    int t = j >> 5, r = j & 31;
    const float* W    = (t == 0) ? Wq : (t == 1) ? Wk : Wv;
    const float* bias = (t == 0) ? bq : (t == 1) ? bk : bv;
    float b2 = bias[r], sw = 0.f;
    #pragma unroll
    for (int d = 0; d < DIM; d++) {
        float w  = W[r * DIM + d];
        float gw = w * ln_g[d];
        b2 = fmaf(w, ln_b[d], b2);
        sw += gw;
        gWfold[(t * DIM + r) * DIM + d] = gw;
    }
    gB2[j] = b2;
    gSw[j] = sw;
}

__global__ __launch_bounds__(NTHR, 4) void mha_fused_kernel(
    const float* __restrict__ Q, const float* __restrict__ K, const float* __restrict__ V,
    const float* __restrict__ Wo, const float* __restrict__ bo,
    float* __restrict__ out)
{
    __shared__ __align__(16) float sbuf[3 * SEQ * PITCH];  // projected q,k,v; q region becomes ctx
    __shared__ float sW[4 * DIM * 33];                     // folded Wq,Wk,Wv + raw Wo, pitch 33
    __shared__ float2 sStats[3 * SEQ];                     // (mu, inv) per row
    __shared__ float sB2[3 * DIM], sSw[3 * DIM], sboS[DIM];

    const int tid  = threadIdx.x;
    const int lane = tid & 31;
    const int wid  = tid >> 5;          // 0..3
    const int hw   = lane >> 4;         // half-warp: row selector
    const int cc   = lane & 15;         // column (this lane owns cols cc and cc+16)
    const size_t boff = (size_t)blockIdx.x * (SEQ * DIM);
    const float* Qb = Q + boff;
    const float* Kb = K + boff;
    const float* Vb = V + boff;

    // ---- stage weights into padded smem ----
    for (int i = tid; i < 4 * DIM * DIM; i += NTHR) {
        int t = i >> 10, idx = i & 1023, r = idx >> 5, c = idx & 31;
        sW[t * DIM * 33 + r * 33 + c] = (t < 3) ? gWfold[i] : Wo[idx];
    }
    if (tid < 3 * DIM) { sB2[tid] = gB2[tid]; sSw[tid] = gSw[tid]; }
    else if (tid < 4 * DIM) sboS[tid - 3 * DIM] = bo[tid - 3 * DIM];

    // ---- LN stats only (raw x is NOT staged; re-read from gmem/L1 later) ----
    {
        const int rsub = lane >> 3;   // 0..3: row within 4-row block
        const int rk   = lane & 7;    // float4 segment within row
        for (int blk = wid; blk < (3 * SEQ + 3) / 4; blk += 4) {
            int gr = blk * 4 + rsub;
            float4 xv = make_float4(0.f, 0.f, 0.f, 0.f);
            if (gr < 3 * SEQ) {
                int t = gr / SEQ;
                int r = gr - t * SEQ;
                const float* src = (t == 0) ? Qb : (t == 1) ? Kb : Vb;
                xv = *(const float4*)(src + r * DIM + rk * 4);
            }
            float s1 = xv.x + xv.y + xv.z + xv.w;
            float s2 = xv.x * xv.x + xv.y * xv.y + xv.z * xv.z + xv.w * xv.w;
            #pragma unroll
            for (int o = 4; o; o >>= 1) {
                s1 += __shfl_xor_sync(FULLM, s1, o);
                s2 += __shfl_xor_sync(FULLM, s2, o);
            }
            if (rk == 0 && gr < 3 * SEQ) {
                float mu  = s1 * (1.0f / DIM);
                float var = s2 * (1.0f / DIM) - mu * mu;
                sStats[gr] = make_float2(mu, rsqrtf(var + 1e-5f));
            }
        }
    }
    __syncthreads();

    // ---- projections, C=2 tiling: lane computes cols {cc, cc+16}; half-warps = 2 rows/step
    // out[s][j] = inv_s*(dot(x_s, W'_j) - mu_s*sw_j) + b2_j ; x read from gmem (L1-hot)
    {
        float wreg0[DIM], wreg1[DIM];
        float b20 = 0.f, b21 = 0.f, sw0 = 0.f, sw1 = 0.f;
        int tprev = -1;
        #pragma unroll
        for (int k = 0; k < 6; k++) {
            const int task = wid * 6 + k;       // 24 tasks: 3 tensors x 8 chunks
            const int t = task >> 3;
            const int c = task & 7;
            if (t != tprev) {
                const float* w0 = sW + (t * DIM + cc) * 33;
                const float* w1 = sW + (t * DIM + cc + 16) * 33;
                #pragma unroll
                for (int d = 0; d < DIM; d++) { wreg0[d] = w0[d]; wreg1[d] = w1[d]; }
                b20 = sB2[t * DIM + cc]; b21 = sB2[t * DIM + cc + 16];
                sw0 = sSw[t * DIM + cc]; sw1 = sSw[t * DIM + cc + 16];
                tprev = t;
            }
            const int r0 = (c * SEQ) >> 3;
            const int r1 = ((c + 1) * SEQ) >> 3;
            const float* src = (t == 0) ? Qb : (t == 1) ? Kb : Vb;
            for (int ra = r0; ra < r1; ra += 2) {
                const int myrow = ra + hw;
                const int mr = (myrow < r1) ? myrow : (r1 - 1);
                const float4* xr = (const float4*)(src + mr * DIM);
                float a0 = 0.f, a1 = 0.f, a2 = 0.f, a3 = 0.f;   // 4 chains
                #pragma unroll
                for (int d4 = 0; d4 < 8; d4 += 2) {
                    float4 x0 = __ldg(xr + d4);
                    float4 x1 = __ldg(xr + d4 + 1);
                    a0 = fmaf(x0.x, wreg0[d4*4+0], fmaf(x0.y, wreg0[d4*4+1],
                         fmaf(x0.z, wreg0[d4*4+2], fmaf(x0.w, wreg0[d4*4+3], a0))));
                    a1 = fmaf(x0.x, wreg1[d4*4+0], fmaf(x0.y, wreg1[d4*4+1],
                         fmaf(x0.z, wreg1[d4*4+2], fmaf(x0.w, wreg1[d4*4+3], a1))));
                    a2 = fmaf(x1.x, wreg0[d4*4+4], fmaf(x1.y, wreg0[d4*4+5],
                         fmaf(x1.z, wreg0[d4*4+6], fmaf(x1.w, wreg0[d4*4+7], a2))));
                    a3 = fmaf(x1.x, wreg1[d4*4+4], fmaf(x1.y, wreg1[d4*4+5],
                         fmaf(x1.z, wreg1[d4*4+6], fmaf(x1.w, wreg1[d4*4+7], a3))));
                }
                float dot0 = a0 + a2, dot1 = a1 + a3;
                float2 st = sStats[t * SEQ + mr];
                float o0 = fmaf(st.y, fmaf(-st.x, sw0, dot0), b20);
                float o1 = fmaf(st.y, fmaf(-st.x, sw1, dot1), b21);
                if (myrow < r1) {
                    float* drow = sbuf + (t * SEQ + mr) * PITCH;
                    drow[cc] = o0; drow[cc + 16] = o1;
                }
            }
        }
    }
    __syncthreads();

    // ---- paired causal attention: thread = (head, pair p), queries p and 49-p ----
    if (tid < 4 * (SEQ / 2)) {
        const int h = tid & 3;
        const int p = tid >> 2;           // 0..24
        const int i2 = SEQ - 1 - p;       // 25..49
        const float* sk_ = sbuf + SEQ * PITCH;
        const float* sv_ = sbuf + 2 * SEQ * PITCH;
        const float scale = 0.35355339059327373f;  // 1/sqrt(8)

        const float* q1p = sbuf + p  * PITCH + h * 8;
        const float* q2p = sbuf + i2 * PITCH + h * 8;
        float4 q1a = *(const float4*)q1p, q1b = *(const float4*)(q1p + 4);
        float4 q2a = *(const float4*)q2p, q2b = *(const float4*)(q2p + 4);
        q1a.x *= scale; q1a.y *= scale; q1a.z *= scale; q1a.w *= scale;
        q1b.x *= scale; q1b.y *= scale; q1b.z *= scale; q1b.w *= scale;
        q2a.x *= scale; q2a.y *= scale; q2a.z *= scale; q2a.w *= scale;
        q2b.x *= scale; q2b.y *= scale; q2b.z *= scale; q2b.w *= scale;

        float ssum1 = 0.f, ssum2 = 0.f;
        float4 a1a = make_float4(0.f,0.f,0.f,0.f), a1b = make_float4(0.f,0.f,0.f,0.f);
        float4 a2a = make_float4(0.f,0.f,0.f,0.f), a2b = make_float4(0.f,0.f,0.f,0.f);

        for (int j = 0; j <= i2; j++) {
            const float* kr = sk_ + j * PITCH + h * 8;
            float4 k0 = *(const float4*)kr;
            float4 k1 = *(const float4*)(kr + 4);
            const float* vr = sv_ + j * PITCH + h * 8;
            float4 v0 = *(const float4*)vr;
            float4 v1 = *(const float4*)(vr + 4);

            float d2 = q2a.x*k0.x + q2a.y*k0.y + q2a.z*k0.z + q2a.w*k0.w
                     + q2b.x*k1.x + q2b.y*k1.y + q2b.z*k1.z + q2b.w*k1.w;
            float w2 = __expf(d2);
            ssum2 += w2;
            a2a.x = fmaf(w2, v0.x, a2a.x); a2a.y = fmaf(w2, v0.y, a2a.y);
            a2a.z = fmaf(w2, v0.z, a2a.z); a2a.w = fmaf(w2, v0.w, a2a.w);
            a2b.x = fmaf(w2, v1.x, a2b.x); a2b.y = fmaf(w2, v1.y, a2b.y);
            a2b.z = fmaf(w2, v1.z, a2b.z); a2b.w = fmaf(w2, v1.w, a2b.w);

            if (j <= p) {
                float d1 = q1a.x*k0.x + q1a.y*k0.y + q1a.z*k0.z + q1a.w*k0.w
                         + q1b.x*k1.x + q1b.y*k1.y + q1b.z*k1.z + q1b.w*k1.w;
                float w1 = __expf(d1);
                ssum1 += w1;
                a1a.x = fmaf(w1, v0.x, a1a.x); a1a.y = fmaf(w1, v0.y, a1a.y);
                a1a.z = fmaf(w1, v0.z, a1a.z); a1a.w = fmaf(w1, v0.w, a1a.w);
                a1b.x = fmaf(w1, v1.x, a1b.x); a1b.y = fmaf(w1, v1.y, a1b.y);
                a1b.z = fmaf(w1, v1.z, a1b.z); a1b.w = fmaf(w1, v1.w, a1b.w);
            }
        }
        float inv1 = 1.0f / ssum1;
        float inv2 = 1.0f / ssum2;
        a1a.x *= inv1; a1a.y *= inv1; a1a.z *= inv1; a1a.w *= inv1;
        a1b.x *= inv1; a1b.y *= inv1; a1b.z *= inv1; a1b.w *= inv1;
        a2a.x *= inv2; a2a.y *= inv2; a2a.z *= inv2; a2a.w *= inv2;
        a2b.x *= inv2; a2b.y *= inv2; a2b.z *= inv2; a2b.w *= inv2;

        float* c1 = sbuf + p  * PITCH + h * 8;
        float* c2 = sbuf + i2 * PITCH + h * 8;
        *(float4*)c1 = a1a; *(float4*)(c1 + 4) = a1b;
        *(float4*)c2 = a2a; *(float4*)(c2 + 4) = a2b;
    }
    __syncthreads();

    // ---- output projection + residual, C=2 tiling (Wo register-resident) ----
    {
        float wreg0[DIM], wreg1[DIM];
        const float* w0 = sW + (3 * DIM + cc) * 33;
        const float* w1 = sW + (3 * DIM + cc + 16) * 33;
        #pragma unroll
        for (int d = 0; d < DIM; d++) { wreg0[d] = w0[d]; wreg1[d] = w1[d]; }
        const float b0 = sboS[cc], b1 = sboS[cc + 16];
        float* ob = out + boff;
        const int r0 = (wid * SEQ) >> 2;
        const int r1 = ((wid + 1) * SEQ) >> 2;
        for (int ra = r0; ra < r1; ra += 2) {
            const int myrow = ra + hw;
            const int mr = (myrow < r1) ? myrow : (r1 - 1);
            const float4* xr = (const float4*)(sbuf + mr * PITCH);
            float a0 = 0.f, a1 = 0.f, a2 = 0.f, a3 = 0.f;
            #pragma unroll
            for (int d4 = 0; d4 < 8; d4 += 2) {
                float4 x0 = xr[d4];
                float4 x1 = xr[d4 + 1];
                a0 = fmaf(x0.x, wreg0[d4*4+0], fmaf(x0.y, wreg0[d4*4+1],
                     fmaf(x0.z, wreg0[d4*4+2], fmaf(x0.w, wreg0[d4*4+3], a0))));
                a1 = fmaf(x0.x, wreg1[d4*4+0], fmaf(x0.y, wreg1[d4*4+1],
                     fmaf(x0.z, wreg1[d4*4+2], fmaf(x0.w, wreg1[d4*4+3], a1))));
                a2 = fmaf(x1.x, wreg0[d4*4+4], fmaf(x1.y, wreg0[d4*4+5],
                     fmaf(x1.z, wreg0[d4*4+6], fmaf(x1.w, wreg0[d4*4+7], a2))));
                a3 = fmaf(x1.x, wreg1[d4*4+4], fmaf(x1.y, wreg1[d4*4+5],
                     fmaf(x1.z, wreg1[d4*4+6], fmaf(x1.w, wreg1[d4*4+7], a3))));
            }
            float o0 = (a0 + a2) + b0 + Qb[mr * DIM + cc];
            float o1 = (a1 + a3) + b1 + Qb[mr * DIM + cc + 16];
            if (myrow < r1) {
                ob[mr * DIM + cc]      = o0;
                ob[mr * DIM + cc + 16] = o1;
            }
        }
    }
}

extern "C" void kernel_launch(void* const* d_in, const int* in_sizes, int n_in,
                              void* d_out, int out_size) {
    const float* Q    = (const float*)d_in[0];
    const float* K    = (const float*)d_in[1];
    const float* V    = (const float*)d_in[2];
    // d_in[3] = mask (static causal triu, implemented analytically)
    const float* ln_g = (const float*)d_in[4];
    const float* ln_b = (const float*)d_in[5];
    const float* Wq   = (const float*)d_in[6];
    const float* bq   = (const float*)d_in[7];
    const float* Wk   = (const float*)d_in[8];
    const float* bk   = (const float*)d_in[9];
    const float* Wv   = (const float*)d_in[10];
    const float* bv   = (const float*)d_in[11];
    const float* Wo   = (const float*)d_in[12];
    const float* bo   = (const float*)d_in[13];
    float* out = (float*)d_out;

    const int B = in_sizes[0] / (SEQ * DIM);  // 16384
    prep_kernel<<<1, 96>>>(ln_g, ln_b, Wq, bq, Wk, bk, Wv, bv);
    mha_fused_kernel<<<B, NTHR>>>(Q, K, V, Wo, bo, out);
}